// round 4
// baseline (speedup 1.0000x reference)
#include <cuda_runtime.h>
#include <cstdint>

// 2D Haar DWT, fp32, input (8, 64, 512, 512) -> 4x (8, 64, 256, 256)
// Output d_out = [ll | lh | hl | hh], each 8*64*256*256 floats.
//
// HBM-bound at ~6.8 TB/s (86% of spec). R3: persistent grid-stride kernel,
// exactly one wave (148 SMs x 8 CTAs x 256 thr), each thread loops over
// work items -> no wave transitions, loads of next iter overlap stores of
// current iter. Butterfly math (12 ops instead of 16).

#define PLANES      512          // 8 * 64
#define IN_W        512
#define OUT_W       256
#define OUT_H       256
#define PLANE_IN_F4   (IN_W * 512 / 4)     // 65536 float4 per input plane
#define ROW_IN_F4     (IN_W / 4)           // 128 float4 per input row
#define PLANE_OUT_F4  (OUT_W * OUT_H / 4)  // 16384 float4 per output plane
#define ROW_OUT_F4    (OUT_W / 4)          // 64 float4 per output row
#define SUBBAND_ELEMS (PLANES * OUT_W * OUT_H)  // 33554432 floats per subband
#define TOTAL_ITEMS   (PLANES * OUT_H * ROW_OUT_F4)  // 8,388,608 work items

#define GRID_CTAS   1184         // 148 SMs * 8 resident CTAs = one wave
#define BLOCK_THR   256

__global__ __launch_bounds__(BLOCK_THR)
void dwt2d_haar_kernel(const float4* __restrict__ x4,
                       float4* __restrict__ ll,
                       float4* __restrict__ lh,
                       float4* __restrict__ hl,
                       float4* __restrict__ hh)
{
    const unsigned stride = GRID_CTAS * BLOCK_THR;     // 303,104
    unsigned tid = blockIdx.x * BLOCK_THR + threadIdx.x;

    const float half = 0.5f;

    for (unsigned item = tid; item < TOTAL_ITEMS; item += stride) {
        unsigned ox4 = item & (ROW_OUT_F4 - 1);        // 0..63
        unsigned t1  = item >> 6;
        unsigned oy  = t1 & (OUT_H - 1);               // 0..255
        unsigned p   = t1 >> 8;                        // 0..511

        unsigned in_base = p * PLANE_IN_F4 + (2u * oy) * ROW_IN_F4 + 2u * ox4;

        float4 r0a = x4[in_base];                 // row 2y,   cols 8x..8x+3
        float4 r0b = x4[in_base + 1];             // row 2y,   cols 8x+4..8x+7
        float4 r1a = x4[in_base + ROW_IN_F4];     // row 2y+1, cols 8x..8x+3
        float4 r1b = x4[in_base + ROW_IN_F4 + 1]; // row 2y+1, cols 8x+4..8x+7

        float4 vll, vlh, vhl, vhh;
        {
            // pixel k: a=top-even, b=top-odd, c=bot-even, d=bot-odd
            // butterfly: u = a+b, v = c+d, w = b-a (hmm use direct pairs)
            // ll = ((a+b)+(c+d))*h ; lh = ((c+d)-(a+b))*h
            // hl = ((b-a)+(d-c))*h ; hh = ((a-b)+(d-c))*h -> check:
            //   hh = (a+d-b-c)*h = ((a-b)+(d-c))*h  ok
            //   hl = (b+d-a-c)*h = ((b-a)+(d-c))*h  ok
            float u0 = r0a.x + r0a.y, v0 = r1a.x + r1a.y;   // a+b, c+d
            float w0 = r0a.y - r0a.x, z0 = r1a.y - r1a.x;   // b-a, d-c
            vll.x = (u0 + v0) * half;  vlh.x = (v0 - u0) * half;
            vhl.x = (w0 + z0) * half;  vhh.x = (z0 - w0) * half;

            float u1 = r0a.z + r0a.w, v1 = r1a.z + r1a.w;
            float w1 = r0a.w - r0a.z, z1 = r1a.w - r1a.z;
            vll.y = (u1 + v1) * half;  vlh.y = (v1 - u1) * half;
            vhl.y = (w1 + z1) * half;  vhh.y = (z1 - w1) * half;

            float u2 = r0b.x + r0b.y, v2 = r1b.x + r1b.y;
            float w2 = r0b.y - r0b.x, z2 = r1b.y - r1b.x;
            vll.z = (u2 + v2) * half;  vlh.z = (v2 - u2) * half;
            vhl.z = (w2 + z2) * half;  vhh.z = (z2 - w2) * half;

            float u3 = r0b.z + r0b.w, v3 = r1b.z + r1b.w;
            float w3 = r0b.w - r0b.z, z3 = r1b.w - r1b.z;
            vll.w = (u3 + v3) * half;  vlh.w = (v3 - u3) * half;
            vhl.w = (w3 + z3) * half;  vhh.w = (z3 - w3) * half;
        }

        unsigned o = p * PLANE_OUT_F4 + oy * ROW_OUT_F4 + ox4;
        ll[o] = vll;
        lh[o] = vlh;
        hl[o] = vhl;
        hh[o] = vhh;
    }
}

extern "C" void kernel_launch(void* const* d_in, const int* in_sizes, int n_in,
                              void* d_out, int out_size)
{
    const float4* x4 = (const float4*)d_in[0];
    float* out = (float*)d_out;

    float4* ll = (float4*)(out + 0ull * SUBBAND_ELEMS);
    float4* lh = (float4*)(out + 1ull * SUBBAND_ELEMS);
    float4* hl = (float4*)(out + 2ull * SUBBAND_ELEMS);
    float4* hh = (float4*)(out + 3ull * SUBBAND_ELEMS);

    dwt2d_haar_kernel<<<GRID_CTAS, BLOCK_THR>>>(x4, ll, lh, hl, hh);
}

// round 5
// speedup vs baseline: 1.2022x; 1.2022x over previous
#include <cuda_runtime.h>
#include <cstdint>

// 2D Haar DWT, fp32, input (8, 64, 512, 512) -> 4x (8, 64, 256, 256)
// Output d_out = [ll | lh | hl | hh], each 8*64*256*256 floats.
//
// R1 shape (best: 156.4us, DRAM 86%) + L1 bypass (.cg) on loads and stores:
// zero reuse, so L1 is pure pass-through overhead. One-shot launch,
// 65536 x 256, one float2 store per subband per thread.

#define PLANES      512          // 8 * 64
#define IN_W        512
#define OUT_W       256
#define OUT_H       256
#define PLANE_IN_F4   (IN_W * 512 / 4)     // 65536 float4 per input plane
#define ROW_IN_F4     (IN_W / 4)           // 128 float4 per input row
#define PLANE_OUT_F2  (OUT_W * OUT_H / 2)  // 32768 float2 per output plane
#define ROW_OUT_F2    (OUT_W / 2)          // 128 float2 per output row
#define SUBBAND_ELEMS (PLANES * OUT_W * OUT_H)  // 33554432 floats per subband

__global__ __launch_bounds__(256)
void dwt2d_haar_kernel(const float4* __restrict__ x4,
                       float2* __restrict__ ll,
                       float2* __restrict__ lh,
                       float2* __restrict__ hl,
                       float2* __restrict__ hh)
{
    // One thread = one (plane, out_row, out_col_pair): reads 2x4 input patch,
    // writes 2 output pixels to each of the 4 subbands.
    unsigned tid = blockIdx.x * blockDim.x + threadIdx.x;
    // total = 512 planes * 256 rows * 128 col-pairs = 16,777,216 (exact grid)

    unsigned ox2 = tid & (ROW_OUT_F2 - 1);          // 0..127
    unsigned t1  = tid >> 7;
    unsigned oy  = t1 & (OUT_H - 1);                // 0..255
    unsigned p   = t1 >> 8;                         // 0..511

    unsigned in_base = p * PLANE_IN_F4 + (2u * oy) * ROW_IN_F4 + ox2;
    float4 r0 = __ldcg(&x4[in_base]);               // row 2y,   cols 4x..4x+3
    float4 r1 = __ldcg(&x4[in_base + ROW_IN_F4]);   // row 2y+1

    // pixel 0: a=x[2y][2x] b=x[2y][2x+1] c=x[2y+1][2x] d=x[2y+1][2x+1]
    float a0 = r0.x, b0 = r0.y, c0 = r1.x, d0 = r1.y;
    float a1 = r0.z, b1 = r0.w, c1 = r1.z, d1 = r1.w;

    const float half = 0.5f;
    float2 vll, vlh, vhl, vhh;
    vll.x = (a0 + b0 + c0 + d0) * half;
    vll.y = (a1 + b1 + c1 + d1) * half;
    vlh.x = (c0 + d0 - a0 - b0) * half;
    vlh.y = (c1 + d1 - a1 - b1) * half;
    vhl.x = (b0 + d0 - a0 - c0) * half;
    vhl.y = (b1 + d1 - a1 - c1) * half;
    vhh.x = (a0 + d0 - b0 - c0) * half;
    vhh.y = (a1 + d1 - b1 - c1) * half;

    unsigned o = p * PLANE_OUT_F2 + oy * ROW_OUT_F2 + ox2;
    __stcg(&ll[o], vll);
    __stcg(&lh[o], vlh);
    __stcg(&hl[o], vhl);
    __stcg(&hh[o], vhh);
}

extern "C" void kernel_launch(void* const* d_in, const int* in_sizes, int n_in,
                              void* d_out, int out_size)
{
    const float4* x4 = (const float4*)d_in[0];
    float* out = (float*)d_out;

    float2* ll = (float2*)(out + 0ull * SUBBAND_ELEMS);
    float2* lh = (float2*)(out + 1ull * SUBBAND_ELEMS);
    float2* hl = (float2*)(out + 2ull * SUBBAND_ELEMS);
    float2* hh = (float2*)(out + 3ull * SUBBAND_ELEMS);

    const unsigned total_threads = PLANES * OUT_H * ROW_OUT_F2;  // 16,777,216
    const unsigned block = 256;
    const unsigned grid = total_threads / block;                 // 65,536

    dwt2d_haar_kernel<<<grid, block>>>(x4, ll, lh, hl, hh);
}

// round 6
// speedup vs baseline: 1.2041x; 1.0016x over previous
#include <cuda_runtime.h>
#include <cstdint>

// 2D Haar DWT, fp32, input (8, 64, 512, 512) -> 4x (8, 64, 256, 256)
// Output d_out = [ll | lh | hl | hh], each 8*64*256*256 floats.
//
// DRAM-saturated at ~6.8 TB/s (86% active). R6: R1 access shape (2x LDG.128
// + 4x STG.64 per thread, one-shot launch) with 512-thread blocks for
// higher resident-warp count / coarser balanced scheduling units.

#define PLANES      512          // 8 * 64
#define IN_W        512
#define OUT_W       256
#define OUT_H       256
#define PLANE_IN_F4   (IN_W * 512 / 4)     // 65536 float4 per input plane
#define ROW_IN_F4     (IN_W / 4)           // 128 float4 per input row
#define PLANE_OUT_F2  (OUT_W * OUT_H / 2)  // 32768 float2 per output plane
#define ROW_OUT_F2    (OUT_W / 2)          // 128 float2 per output row
#define SUBBAND_ELEMS (PLANES * OUT_W * OUT_H)  // 33554432 floats per subband

__global__ __launch_bounds__(512)
void dwt2d_haar_kernel(const float4* __restrict__ x4,
                       float2* __restrict__ ll,
                       float2* __restrict__ lh,
                       float2* __restrict__ hl,
                       float2* __restrict__ hh)
{
    // One thread = one (plane, out_row, out_col_pair): reads 2x4 input patch,
    // writes 2 output pixels to each of the 4 subbands.
    unsigned tid = blockIdx.x * blockDim.x + threadIdx.x;
    // total = 512 planes * 256 rows * 128 col-pairs = 16,777,216 (exact grid)

    unsigned ox2 = tid & (ROW_OUT_F2 - 1);          // 0..127
    unsigned t1  = tid >> 7;
    unsigned oy  = t1 & (OUT_H - 1);                // 0..255
    unsigned p   = t1 >> 8;                         // 0..511

    unsigned in_base = p * PLANE_IN_F4 + (2u * oy) * ROW_IN_F4 + ox2;
    // Front-batched pair of independent 128-bit loads.
    float4 r0 = __ldcg(&x4[in_base]);               // row 2y,   cols 4x..4x+3
    float4 r1 = __ldcg(&x4[in_base + ROW_IN_F4]);   // row 2y+1

    float a0 = r0.x, b0 = r0.y, c0 = r1.x, d0 = r1.y;
    float a1 = r0.z, b1 = r0.w, c1 = r1.z, d1 = r1.w;

    const float half = 0.5f;
    float2 vll, vlh, vhl, vhh;
    vll.x = (a0 + b0 + c0 + d0) * half;
    vll.y = (a1 + b1 + c1 + d1) * half;
    vlh.x = (c0 + d0 - a0 - b0) * half;
    vlh.y = (c1 + d1 - a1 - b1) * half;
    vhl.x = (b0 + d0 - a0 - c0) * half;
    vhl.y = (b1 + d1 - a1 - c1) * half;
    vhh.x = (a0 + d0 - b0 - c0) * half;
    vhh.y = (a1 + d1 - b1 - c1) * half;

    unsigned o = p * PLANE_OUT_F2 + oy * ROW_OUT_F2 + ox2;
    ll[o] = vll;
    lh[o] = vlh;
    hl[o] = vhl;
    hh[o] = vhh;
}

extern "C" void kernel_launch(void* const* d_in, const int* in_sizes, int n_in,
                              void* d_out, int out_size)
{
    const float4* x4 = (const float4*)d_in[0];
    float* out = (float*)d_out;

    float2* ll = (float2*)(out + 0ull * SUBBAND_ELEMS);
    float2* lh = (float2*)(out + 1ull * SUBBAND_ELEMS);
    float2* hl = (float2*)(out + 2ull * SUBBAND_ELEMS);
    float2* hh = (float2*)(out + 3ull * SUBBAND_ELEMS);

    const unsigned total_threads = PLANES * OUT_H * ROW_OUT_F2;  // 16,777,216
    const unsigned block = 512;
    const unsigned grid = total_threads / block;                 // 32,768

    dwt2d_haar_kernel<<<grid, block>>>(x4, ll, lh, hl, hh);
}

// round 7
// speedup vs baseline: 1.2076x; 1.0029x over previous
#include <cuda_runtime.h>
#include <cstdint>

// 2D Haar DWT, fp32, input (8, 64, 512, 512) -> 4x (8, 64, 256, 256)
// Output d_out = [ll | lh | hl | hh], each 8*64*256*256 floats.
//
// R7: block-level read/write phase separation. Phase 1: each thread does
// 2x LDG.128 + compute + stage 4x float2 to smem. Barrier. Phase 2: block
// re-emits output as contiguous STG.128 bursts, one subband per 64-thread
// group (each warp covers 512B contiguous of one subband). Same 1 GiB
// global traffic; longer write bursts to each DRAM row.

#define PLANES      512          // 8 * 64
#define IN_W        512
#define OUT_W       256
#define OUT_H       256
#define PLANE_IN_F4   (IN_W * 512 / 4)     // 65536 float4 per input plane
#define ROW_IN_F4     (IN_W / 4)           // 128 float4 per input row
#define PLANE_OUT_F2  (OUT_W * OUT_H / 2)  // 32768 float2 per output plane
#define ROW_OUT_F2    (OUT_W / 2)          // 128 float2 per output row
#define SUBBAND_ELEMS (PLANES * OUT_W * OUT_H)  // 33554432 floats per subband
#define SUBBAND_F4    (SUBBAND_ELEMS / 4)       // 8388608 float4 per subband

__global__ __launch_bounds__(256)
void dwt2d_haar_kernel(const float4* __restrict__ x4,
                       float4* __restrict__ out4)   // base of d_out as float4
{
    __shared__ float2 s[4][256];   // [subband][item-in-block], 8 KB

    unsigned tid  = threadIdx.x;
    unsigned item = blockIdx.x * 256u + tid;
    // item == output float2 index within each subband (exact identity):
    //   o = p*PLANE_OUT_F2 + oy*ROW_OUT_F2 + ox2 = item

    // ---- Phase 1: load 2x4 patch, compute, stage to smem ----
    unsigned ox2 = item & (ROW_OUT_F2 - 1);         // 0..127
    unsigned t1  = item >> 7;
    unsigned oy  = t1 & (OUT_H - 1);                // 0..255
    unsigned p   = t1 >> 8;                         // 0..511

    unsigned in_base = p * PLANE_IN_F4 + (2u * oy) * ROW_IN_F4 + ox2;
    float4 r0 = __ldcg(&x4[in_base]);               // row 2y,   cols 4x..4x+3
    float4 r1 = __ldcg(&x4[in_base + ROW_IN_F4]);   // row 2y+1

    float a0 = r0.x, b0 = r0.y, c0 = r1.x, d0 = r1.y;
    float a1 = r0.z, b1 = r0.w, c1 = r1.z, d1 = r1.w;

    const float half = 0.5f;
    float2 vll, vlh, vhl, vhh;
    vll.x = (a0 + b0 + c0 + d0) * half;
    vll.y = (a1 + b1 + c1 + d1) * half;
    vlh.x = (c0 + d0 - a0 - b0) * half;
    vlh.y = (c1 + d1 - a1 - b1) * half;
    vhl.x = (b0 + d0 - a0 - c0) * half;
    vhl.y = (b1 + d1 - a1 - c1) * half;
    vhh.x = (a0 + d0 - b0 - c0) * half;
    vhh.y = (a1 + d1 - b1 - c1) * half;

    s[0][tid] = vll;
    s[1][tid] = vlh;
    s[2][tid] = vhl;
    s[3][tid] = vhh;

    __syncthreads();

    // ---- Phase 2: burst-emit. 64 threads per subband, 2x STG.128 each. ----
    unsigned sub = tid >> 6;            // 0..3
    unsigned idx = tid & 63u;           // 0..63

    // block owns float4 range [blockIdx.x*128, +128) in each subband
    unsigned base4 = blockIdx.x * 128u;
    float4* outp = out4 + (size_t)sub * SUBBAND_F4;

    const float4* srow = (const float4*)&s[sub][0];   // 128 float4 staged
    float4 v0 = srow[idx];
    float4 v1 = srow[idx + 64];

    outp[base4 + idx]      = v0;
    outp[base4 + 64 + idx] = v1;
}

extern "C" void kernel_launch(void* const* d_in, const int* in_sizes, int n_in,
                              void* d_out, int out_size)
{
    const float4* x4 = (const float4*)d_in[0];
    float4* out4 = (float4*)d_out;

    const unsigned total_threads = PLANES * OUT_H * ROW_OUT_F2;  // 16,777,216
    const unsigned block = 256;
    const unsigned grid = total_threads / block;                 // 65,536

    dwt2d_haar_kernel<<<grid, block>>>(x4, out4);
}